// round 15
// baseline (speedup 1.0000x reference)
#include <cuda_runtime.h>
#include <cuda_fp16.h>
#include <cstdint>

// Problem constants
#define B_ 128
#define T_ 100
#define I_ 1024
#define O_ 1024
#define EPSV 1e-8f
#define LO_SCALE 2048.0f        // 2^11
#define LO_INV   (1.0f / 2048.0f)

// Scratch (__device__ globals; referenced ONLY in device code — R6 lesson)
__device__ __align__(16) float  g_h[(size_t)B_ * T_ * O_];     // h = x@w
__device__ __align__(16) float  g_d[(size_t)O_ * O_];          // d = w^T w
__device__ __align__(16) float  g_inv[O_];                     // 1/(norm+eps)
__device__ int    g_cnt[T_];                                   // per-step spike counts
__device__ __align__(16) __half g_xh16[(size_t)B_ * T_ * I_];  // x hi fp16
__device__ __align__(16) __half g_xl16[(size_t)B_ * T_ * I_];  // (x-hi)*2^11 fp16
__device__ __align__(16) __half g_wTh16[(size_t)O_ * I_];      // w^T hi, [o][a]
__device__ __align__(16) __half g_wTl16[(size_t)O_ * I_];      // w^T lo*2^11

// ---------------------------------------------------------------------------
// helpers (plain sm_80-class PTX — harness targets sm_103 w/o 'a')
// ---------------------------------------------------------------------------
__device__ __forceinline__ uint32_t smem_u32(const void* p) {
    uint32_t a;
    asm("{ .reg .u64 t; cvta.to.shared.u64 t, %1; cvt.u32.u64 %0, t; }" : "=r"(a) : "l"(p));
    return a;
}
__device__ __forceinline__ void cp16(uint32_t dst, const void* src) {
    asm volatile("cp.async.cg.shared.global [%0], [%1], 16;" :: "r"(dst), "l"(src));
}
#define CP_COMMIT() asm volatile("cp.async.commit_group;" ::: "memory")
#define CP_WAIT(n)  asm volatile("cp.async.wait_group %0;" :: "n"(n) : "memory")

__device__ __forceinline__ void mma_f16(float c[4], const uint32_t a[4],
                                        const uint32_t b[2]) {
    asm volatile(
        "mma.sync.aligned.m16n8k16.row.col.f32.f16.f16.f32 "
        "{%0,%1,%2,%3}, {%4,%5,%6,%7}, {%8,%9}, {%0,%1,%2,%3};"
        : "+f"(c[0]), "+f"(c[1]), "+f"(c[2]), "+f"(c[3])
        : "r"(a[0]), "r"(a[1]), "r"(a[2]), "r"(a[3]), "r"(b[0]), "r"(b[1]));
}

__device__ __forceinline__ void split16(float v, __half& hi, __half& lo) {
    hi = __float2half_rn(v);
    lo = __float2half_rn((v - __half2float(hi)) * LO_SCALE);
}

// ---------------------------------------------------------------------------
// split_x_f16: x -> (g_xh16, g_xl16), elementwise
// ---------------------------------------------------------------------------
__global__ void split_x_f16(const float* __restrict__ src)
{
    const int n4 = (B_ * T_ * I_) / 4;
    const float4* s4 = (const float4*)src;
    uint2* h2 = (uint2*)g_xh16;    // 4 halves per uint2
    uint2* l2 = (uint2*)g_xl16;
    for (int i = blockIdx.x * blockDim.x + threadIdx.x; i < n4;
         i += gridDim.x * blockDim.x) {
        float4 v = s4[i];
        __half h0, h1, h2v, h3, l0, l1, l2v, l3;
        split16(v.x, h0, l0); split16(v.y, h1, l1);
        split16(v.z, h2v, l2v); split16(v.w, h3, l3);
        uint2 ho, lo_;
        ho.x = (uint32_t)__half_as_ushort(h0) | ((uint32_t)__half_as_ushort(h1) << 16);
        ho.y = (uint32_t)__half_as_ushort(h2v) | ((uint32_t)__half_as_ushort(h3) << 16);
        lo_.x = (uint32_t)__half_as_ushort(l0) | ((uint32_t)__half_as_ushort(l1) << 16);
        lo_.y = (uint32_t)__half_as_ushort(l2v) | ((uint32_t)__half_as_ushort(l3) << 16);
        h2[i] = ho; l2[i] = lo_;
    }
}

// ---------------------------------------------------------------------------
// split_wT_f16: w[a][o] -> wT hi/lo fp16 [o][a] (32x32 smem transpose)
// ---------------------------------------------------------------------------
__global__ void split_wT_f16(const float* __restrict__ w)
{
    __shared__ float tile[32][33];
    const int bx = blockIdx.x * 32;   // o
    const int by = blockIdx.y * 32;   // a
    const int tx = threadIdx.x, ty = threadIdx.y;
#pragma unroll
    for (int j = 0; j < 4; j++)
        tile[ty + j * 8][tx] = w[(size_t)(by + ty + j * 8) * O_ + bx + tx];
    __syncthreads();
#pragma unroll
    for (int j = 0; j < 4; j++) {
        float v = tile[tx][ty + j * 8];        // w[a=by+tx][o=bx+ty+j*8]
        __half hi, lo;
        split16(v, hi, lo);
        size_t dst = (size_t)(bx + ty + j * 8) * I_ + by + tx;
        g_wTh16[dst] = hi;
        g_wTl16[dst] = lo;
    }
}

// ---------------------------------------------------------------------------
// gemm_fused: fp16 3-term mma (m16n8k16), BK=32 (2 k-subchunks per stage).
//   y < 100 : g_h[M=12800,N=1024] = x * w        (A = x-split)
//   y >= 100: g_d[1024,1024]      = w^T w        (A = wT-split)
// B is always the wT-split ([n][k], k-contiguous).
// CTA 128x128, 512 threads, 16 warps (4m x 4n), 4-stage cp.async (160 KB).
// SMEM rows: 32 halves (16 words) padded to 20 words -> banks (20g+t4+koff)
// all-distinct mod 32 for both k-subchunks.
// ---------------------------------------------------------------------------
#define SROW  20                    // words per tile row
#define TILEW (128 * SROW)          // 2560 words per tile
#define AHW 0
#define ALW TILEW
#define BHW (2 * TILEW)
#define BLW (3 * TILEW)
#define STGW (4 * TILEW)            // 10240 words = 40KB per stage
#define NCHUNK 32                   // K / 32
#define GF_SMEM_BYTES (4 * STGW * 4)  // 163840 B

__global__ void __launch_bounds__(512) gemm_fused()
{
    extern __shared__ uint32_t smw[];
    const uint32_t sbase = smem_u32(smw);
    const int tid  = threadIdx.x;
    const int wid  = tid >> 5;
    const int lane = tid & 31;
    const int g    = lane >> 2;
    const int t4   = lane & 3;
    const bool is_h = (blockIdx.y < 100);
    const int bm   = (is_h ? blockIdx.y : (blockIdx.y - 100)) * 128;
    const int bn   = blockIdx.x * 128;
    const int wm   = (wid >> 2) * 32;
    const int wn   = (wid & 3) * 32;

    // producer: pr = row 0..127, sub selects tile (0=Ah,1=Al,2=Bh,3=Bl);
    // each thread copies one full 64B row segment (4x cp16) per stage.
    const int pr  = tid >> 2;
    const int sub = tid & 3;
    const __half* psrc;
    uint32_t toff;
    if (sub == 0)      { psrc = (is_h ? g_xh16 : g_wTh16) + (size_t)(bm + pr) * I_; toff = AHW; }
    else if (sub == 1) { psrc = (is_h ? g_xl16 : g_wTl16) + (size_t)(bm + pr) * I_; toff = ALW; }
    else if (sub == 2) { psrc = g_wTh16 + (size_t)(bn + pr) * I_; toff = BHW; }
    else               { psrc = g_wTl16 + (size_t)(bn + pr) * I_; toff = BLW; }
    const uint32_t pdst = sbase + (toff + pr * SROW) * 4;

    float acch[2][4][4], accm[2][4][4];
#pragma unroll
    for (int i = 0; i < 2; i++)
#pragma unroll
        for (int j = 0; j < 4; j++)
#pragma unroll
            for (int q = 0; q < 4; q++) { acch[i][j][q] = 0.f; accm[i][j][q] = 0.f; }

    auto fill = [&](int stage, int chunk) {
        const uint32_t so = stage * (STGW * 4);
        const int k0 = chunk * 32;
#pragma unroll
        for (int j = 0; j < 4; j++)
            cp16(pdst + so + j * 16, psrc + k0 + j * 8);
        CP_COMMIT();
    };

    auto compute = [&](int stage) {
        const uint32_t* base = smw + stage * STGW;
        const uint32_t* Ah = base + AHW;
        const uint32_t* Al = base + ALW;
        const uint32_t* Bh = base + BHW;
        const uint32_t* Bl = base + BLW;
#pragma unroll
        for (int kk = 0; kk < 2; kk++) {
            const int ko = kk * 8;               // word offset of k-subchunk
            uint32_t ah[2][4], al[2][4], bh[4][2], bl[4][2];
#pragma unroll
            for (int mt = 0; mt < 2; mt++) {
                const int r0 = (wm + mt * 16 + g) * SROW + ko;
                const int r1 = r0 + 8 * SROW;
                ah[mt][0] = Ah[r0 + t4];     ah[mt][1] = Ah[r1 + t4];
                ah[mt][2] = Ah[r0 + t4 + 4]; ah[mt][3] = Ah[r1 + t4 + 4];
                al[mt][0] = Al[r0 + t4];     al[mt][1] = Al[r1 + t4];
                al[mt][2] = Al[r0 + t4 + 4]; al[mt][3] = Al[r1 + t4 + 4];
            }
#pragma unroll
            for (int nt = 0; nt < 4; nt++) {
                const int c0 = (wn + nt * 8 + g) * SROW + ko;
                bh[nt][0] = Bh[c0 + t4]; bh[nt][1] = Bh[c0 + t4 + 4];
                bl[nt][0] = Bl[c0 + t4]; bl[nt][1] = Bl[c0 + t4 + 4];
            }
#pragma unroll
            for (int mt = 0; mt < 2; mt++)
#pragma unroll
                for (int nt = 0; nt < 4; nt++) {
                    mma_f16(acch[mt][nt], ah[mt], bh[nt]);
                    mma_f16(accm[mt][nt], ah[mt], bl[nt]);
                    mma_f16(accm[mt][nt], al[mt], bh[nt]);
                }
        }
    };

    fill(0, 0);
    fill(1, 1);
    fill(2, 2);

    for (int c = 0; c < NCHUNK; c++) {
        CP_WAIT(2);                 // chunk c resident (3 groups in flight)
        __syncthreads();
        compute(c & 3);
        if (c + 3 < NCHUNK) fill((c + 3) & 3, c + 3);
        else CP_COMMIT();           // keep wait-count invariant
    }

    // epilogue: h = acc_hi + acc_mid * 2^-11
    float* dst = is_h ? g_h : g_d;
#pragma unroll
    for (int mt = 0; mt < 2; mt++)
#pragma unroll
        for (int nt = 0; nt < 4; nt++) {
            const int row0 = bm + wm + mt * 16 + g;
            const int col  = bn + wn + nt * 8 + t4 * 2;
            float* a = acch[mt][nt];
            float* m = accm[mt][nt];
            *(float2*)&dst[(size_t)row0 * O_ + col] =
                make_float2(a[0] + m[0] * LO_INV, a[1] + m[1] * LO_INV);
            *(float2*)&dst[(size_t)(row0 + 8) * O_ + col] =
                make_float2(a[2] + m[2] * LO_INV, a[3] + m[3] * LO_INV);
        }
}

// ---------------------------------------------------------------------------
// prep: inv_norm from diag(d), zero per-step counters
// ---------------------------------------------------------------------------
__global__ void prep_kernel()
{
    int idx = blockIdx.x * blockDim.x + threadIdx.x;
    if (idx < O_) g_inv[idx] = 1.0f / (g_d[(size_t)idx * O_ + idx] + EPSV);
    if (idx < T_) g_cnt[idx] = 0;
}

// ---------------------------------------------------------------------------
// Scan: one CTA per batch, 1024 threads, one neuron per thread; sparse-exact.
// ---------------------------------------------------------------------------
__global__ void __launch_bounds__(1024) scan_kernel(
    const float* __restrict__ V,
    const float* __restrict__ bb,
    const float* __restrict__ beta_p,
    float* __restrict__ out)
{
    const int b = blockIdx.x;
    const int o = threadIdx.x;
    const float beta = beta_p[0];
    const float ombeta = 1.0f - beta;

    __shared__ int act[2][O_];
    __shared__ int nact[2];
    __shared__ int scnt;

    if (o < 2) nact[o] = 0;
    if (o == 0) scnt = 0;

    float mem = 0.f;
    const float inv = g_inv[o];
    const float bo  = bb[o];
    const float* hrow = g_h + (size_t)b * T_ * O_ + o;
    float*       orow = out + (size_t)b * T_ * O_ + o;

    float h_next = hrow[0];
    __syncthreads();

    int cur = 0;
    for (int t = 0; t < T_; t++) {
        const float h_cur = h_next;
        if (t + 1 < T_) h_next = hrow[(size_t)(t + 1) * O_];

        const int na = nact[cur];
        float rst = 0.f, rec = 0.f;
        for (int a = 0; a < na; a++) {
            const int i = act[cur][a];
            rst += g_d[(size_t)i * O_ + o];
            rec += V[(size_t)i * O_ + o];
        }

        mem = (mem - rst) * beta + (h_cur + rec) * ombeta;
        const float mthr = mem * inv - bo;
        const float s = (mthr > 0.f) ? 1.0f : 0.0f;
        orow[(size_t)t * O_] = s;
        if (s != 0.f) {
            const int p = atomicAdd(&nact[cur ^ 1], 1);
            act[cur ^ 1][p] = o;
            atomicAdd(&scnt, 1);
        }
        __syncthreads();
        if (o == 0) {
            if (scnt) { atomicAdd(&g_cnt[t], scnt); scnt = 0; }
            nact[cur] = 0;
        }
        cur ^= 1;
        __syncthreads();
    }
}

// ---------------------------------------------------------------------------
// finalize: loss and spike-spread scalars
// ---------------------------------------------------------------------------
__global__ void finalize_kernel(float* __restrict__ out, int out_size)
{
    __shared__ int s_tot[128];
    __shared__ int s_max[128];
    const int tid = threadIdx.x;
    int tot = 0, mx = 0;
    for (int t = tid; t < T_; t += 128) {
        int c = g_cnt[t];
        tot += c;
        mx = (c > mx) ? c : mx;
    }
    s_tot[tid] = tot; s_max[tid] = mx;
    __syncthreads();
    for (int s = 64; s > 0; s >>= 1) {
        if (tid < s) {
            s_tot[tid] += s_tot[tid + s];
            s_max[tid] = (s_max[tid + s] > s_max[tid]) ? s_max[tid + s] : s_max[tid];
        }
        __syncthreads();
    }
    if (tid == 0) {
        const size_t base = (size_t)B_ * T_ * O_;
        if ((size_t)out_size >= base + 2) {
            out[base]     = 0.5f * (float)s_tot[0] / (float)((size_t)B_ * T_ * O_);
            out[base + 1] = (float)s_max[0] / (float)(B_ * O_);
        }
    }
}

// ---------------------------------------------------------------------------
extern "C" void kernel_launch(void* const* d_in, const int* in_sizes, int n_in,
                              void* d_out, int out_size)
{
    const float* x    = (const float*)d_in[0];   // [B,T,I]
    const float* w    = (const float*)d_in[1];   // [I,O]
    const float* v    = (const float*)d_in[2];   // [O,O]
    const float* beta = (const float*)d_in[3];   // [1]
    const float* bb   = (const float*)d_in[4];   // [O]
    float* out = (float*)d_out;

    cudaFuncSetAttribute(gemm_fused, cudaFuncAttributeMaxDynamicSharedMemorySize,
                         GF_SMEM_BYTES);

    // 0) fp16 hi/lo splits (x elementwise; w transposed)
    split_x_f16<<<2048, 256>>>(x);
    split_wT_f16<<<dim3(32, 32), dim3(32, 8)>>>(w);

    // 1) fused: h = x@w (y<100) and d = w^T w (y>=100), fp16 3-term, BK=32
    gemm_fused<<<dim3(O_ / 128, 100 + O_ / 128), 512, GF_SMEM_BYTES>>>();

    // 2) inv_norm + zero counters
    prep_kernel<<<4, 256>>>();

    // 3) per-batch recurrent scan
    scan_kernel<<<B_, 1024>>>(v, bb, beta, out);

    // 4) scalar losses
    finalize_kernel<<<1, 128>>>(out, out_size);
}